// round 5
// baseline (speedup 1.0000x reference)
#include <cuda_runtime.h>

#define BN   4
#define LL   512
#define HH   768
#define HSZ  64
#define NOUT 16
#define NTOK (BN*LL)      // 2048
#define NP   131328       // L*(L+1)/2
#define NKQ  16           // split-K factor
#define KQ   (HH/NKQ)     // 48

typedef unsigned long long u64;

// packed fp32x2 helpers (SASS FFMA2 — ptxas never emits this from C++)
__device__ __forceinline__ u64 pk2(float v) {
    u64 r; asm("mov.b64 %0, {%1, %1};" : "=l"(r) : "f"(v)); return r;
}
__device__ __forceinline__ void fma2(u64& d, u64 a, u64 b) {
    asm("fma.rn.f32x2 %0, %1, %2, %0;" : "+l"(d) : "l"(a), "l"(b));
}
__device__ __forceinline__ void upk2(float& lo, float& hi, u64 v) {
    asm("mov.b64 {%0, %1}, %2;" : "=f"(lo), "=f"(hi) : "l"(v));
}

// scratch (allocation-free rule: __device__ globals)
__device__ float g_part[NKQ*NTOK*128]; // 16 MB split-K partials [kq][tok][n]
__device__ float g_q[NTOK*HSZ];        // 512 KB
__device__ float g_k[NTOK*HSZ];        // 512 KB
__device__ float g_A[NTOK*NOUT];       // 128 KB
__device__ float g_E[NTOK*NOUT];       // 128 KB
__device__ float g_S[BN*LL*LL];        // 4 MB

// ---------------------------------------------------------------------------
// Kernel 1: split-K partial GEMM, f32x2 FMA paired along M (tokens).
// Token pairs are contiguous in xs -> the A operand loads directly as a packed
// u64 from shared (no mov). W side packs one scalar at a time (1 live u64).
// acc2[4][8]: 4 token-pairs x 8 cols = 64 fp32 accumulators in 64 regs.
// Grid: 16 token-tiles (128 tok) x 16 K-slices = 256 blocks, 2 blocks/SM.
// ---------------------------------------------------------------------------
__global__ __launch_bounds__(256, 2) void proj_partial_kernel(
    const float* __restrict__ x,
    const float* __restrict__ Wq,
    const float* __restrict__ Wk)
{
    __shared__ float xs[16][132];    // [k][token]  (132: 528B rows, 16B-aligned)
    __shared__ float ws[16][128];    // [k][n] n<64 -> Wq col else Wk col

    const int tid = threadIdx.x;
    const int tt  = blockIdx.x & 15;
    const int kq  = blockIdx.x >> 4;
    const int t0  = tt * 128;
    const int k0  = kq * KQ;
    const int n0  = (tid & 15) * 8;
    const int m0  = (tid >> 4) * 8;

    u64 acc2[4][8];                  // [token-pair][col]
    #pragma unroll
    for (int i = 0; i < 4; i++)
        #pragma unroll
        for (int j = 0; j < 8; j++) acc2[i][j] = 0ull;

    for (int kk = k0; kk < k0 + KQ; kk += 16) {
        #pragma unroll
        for (int p = 0; p < 8; p++) {
            int e = tid + p * 256;
            int tok = e >> 4, d = e & 15;
            xs[d][tok] = x[(t0 + tok) * HH + kk + d];
        }
        #pragma unroll
        for (int p = 0; p < 8; p++) {
            int e = tid + p * 256;
            int n = e & 127, d = e >> 7;
            ws[d][n] = (n < 64) ? Wq[(kk + d) * HSZ + n]
                                : Wk[(kk + d) * HSZ + (n - 64)];
        }
        __syncthreads();
        #pragma unroll
        for (int kd = 0; kd < 16; kd++) {
            ulonglong2 xa = *(const ulonglong2*)&xs[kd][m0];      // tok m0..m0+3
            ulonglong2 xb = *(const ulonglong2*)&xs[kd][m0 + 4];  // tok m0+4..m0+7
            float4 w0 = *(const float4*)&ws[kd][n0];
            float4 w1 = *(const float4*)&ws[kd][n0 + 4];
            u64 x2[4] = {xa.x, xa.y, xb.x, xb.y};
            float wf[8] = {w0.x, w0.y, w0.z, w0.w, w1.x, w1.y, w1.z, w1.w};
            #pragma unroll
            for (int j = 0; j < 8; j++) {
                u64 wp = pk2(wf[j]);
                #pragma unroll
                for (int i = 0; i < 4; i++) fma2(acc2[i][j], x2[i], wp);
            }
        }
        __syncthreads();
    }

    // unpack: acc2[i][j] holds (token m0+2i, token m0+2i+1) at col n0+j
    #pragma unroll
    for (int i = 0; i < 4; i++) {
        float rlo[8], rhi[8];
        #pragma unroll
        for (int j = 0; j < 8; j++) upk2(rlo[j], rhi[j], acc2[i][j]);
        float* gp0 = g_part + ((size_t)kq * NTOK + t0 + m0 + 2*i) * 128 + n0;
        float* gp1 = gp0 + 128;
        *(float4*)&gp0[0] = make_float4(rlo[0], rlo[1], rlo[2], rlo[3]);
        *(float4*)&gp0[4] = make_float4(rlo[4], rlo[5], rlo[6], rlo[7]);
        *(float4*)&gp1[0] = make_float4(rhi[0], rhi[1], rhi[2], rhi[3]);
        *(float4*)&gp1[4] = make_float4(rhi[4], rhi[5], rhi[6], rhi[7]);
    }
}

// ---------------------------------------------------------------------------
// Kernel 2: reduce split-K partials + bias -> g_q/g_k, then A/E tables with
// Wb staged in shared. 64 blocks x 32 tokens. A and E computed in separate
// warp-uniform loops (no divergent serialization).
// A[s,o] = q[s]@Wb[0:64] + bb
// E[e,o] = k[e]@(Wb[64:128]+Wb[192:256]) + q[e]@Wb[128:192]
// ---------------------------------------------------------------------------
__global__ __launch_bounds__(256) void reduce_ae_kernel(
    const float* __restrict__ bq, const float* __restrict__ bk,
    const float* __restrict__ bb, const float* __restrict__ Wb)
{
    __shared__ float Wbs[256 * NOUT];
    __shared__ float sQK[32][132];
    __shared__ float bbs[NOUT];
    __shared__ float bqs[HSZ], bks[HSZ];

    const int tid = threadIdx.x;
    const int t0  = blockIdx.x * 32;

    #pragma unroll
    for (int p = 0; p < 16; p++)
        Wbs[tid + p * 256] = Wb[tid + p * 256];
    if (tid < NOUT) bbs[tid] = bb[tid];
    if (tid < HSZ)  { bqs[tid] = bq[tid]; bks[tid] = bk[tid]; }
    __syncthreads();

    const float4* gp4 = (const float4*)g_part;
    #pragma unroll
    for (int p = 0; p < 4; p++) {
        int e  = tid + p * 256;
        int tok = e >> 5, n4 = e & 31;
        size_t gi = (size_t)(t0 + tok) * 32 + n4;
        float4 v = make_float4(0.f, 0.f, 0.f, 0.f);
        #pragma unroll
        for (int q = 0; q < NKQ; q++) {
            float4 pv = gp4[(size_t)q * NTOK * 32 + gi];
            v.x += pv.x; v.y += pv.y; v.z += pv.z; v.w += pv.w;
        }
        int n = n4 * 4;
        if (n < 64) { v.x += bqs[n]; v.y += bqs[n+1]; v.z += bqs[n+2]; v.w += bqs[n+3]; }
        else        { v.x += bks[n-64]; v.y += bks[n-63]; v.z += bks[n-62]; v.w += bks[n-61]; }
        *(float4*)&sQK[tok][n] = v;
        int tok_g = t0 + tok;
        if (n4 < 16) ((float4*)(g_q + tok_g * HSZ))[n4]      = v;
        else         ((float4*)(g_k + tok_g * HSZ))[n4 - 16] = v;
    }
    __syncthreads();

    // A table: 32 tok x 16 o = 512 items, warp-uniform path
    #pragma unroll
    for (int p = 0; p < 2; p++) {
        int e2   = tid + p * 256;
        int tokL = e2 >> 4;
        int o    = e2 & 15;
        float a = bbs[o];
        #pragma unroll 8
        for (int h = 0; h < 64; h++)
            a += sQK[tokL][h] * Wbs[h * NOUT + o];
        g_A[(t0 + tokL) * NOUT + o] = a;
    }
    // E table: 32 tok x 16 o = 512 items
    #pragma unroll
    for (int p = 0; p < 2; p++) {
        int e2   = tid + p * 256;
        int tokL = e2 >> 4;
        int o    = e2 & 15;
        float a = 0.f;
        #pragma unroll 8
        for (int h = 0; h < 64; h++) {
            a += sQK[tokL][64 + h] * (Wbs[(64 + h) * NOUT + o] + Wbs[(192 + h) * NOUT + o]);
            a += sQK[tokL][h]      *  Wbs[(128 + h) * NOUT + o];
        }
        g_E[(t0 + tokL) * NOUT + o] = a;
    }
}

// ---------------------------------------------------------------------------
// Kernel 3: S[b] = Q[b] @ K[b]^T with f32x2 FMA. 64x64 tiles; below-diagonal
// tiles early-exit.
// ---------------------------------------------------------------------------
__global__ __launch_bounds__(256) void score_kernel()
{
    const int bx = blockIdx.x;   // e tile
    const int by = blockIdx.y;   // s tile
    if (by > bx) return;
    const int b  = blockIdx.z;

    __shared__ float qs[64][68];
    __shared__ float ks[64][68];

    const int tid = threadIdx.x;
    const float* qb = g_q + (b * LL + by * 64) * HSZ;
    const float* kb = g_k + (b * LL + bx * 64) * HSZ;

    #pragma unroll
    for (int p = 0; p < 16; p++) {
        int e = tid + p * 256;
        int r = e >> 6, h = e & 63;
        qs[h][r] = qb[r * HSZ + h];
        ks[h][r] = kb[r * HSZ + h];
    }
    __syncthreads();

    const int m0 = (tid >> 4) * 4;
    const int n0 = (tid & 15) * 4;
    u64 acc2[4][2];
    #pragma unroll
    for (int i = 0; i < 4; i++) { acc2[i][0] = 0ull; acc2[i][1] = 0ull; }

    #pragma unroll
    for (int h = 0; h < 64; h++) {
        float4 a = *(const float4*)&qs[h][m0];
        ulonglong2 vv = *(const ulonglong2*)&ks[h][n0];
        float af[4] = {a.x, a.y, a.z, a.w};
        #pragma unroll
        for (int i = 0; i < 4; i++) {
            u64 am = pk2(af[i]);
            fma2(acc2[i][0], am, vv.x);
            fma2(acc2[i][1], am, vv.y);
        }
    }

    float* Sp = g_S + (size_t)b * LL * LL + (by * 64 + m0) * LL + bx * 64 + n0;
    #pragma unroll
    for (int i = 0; i < 4; i++) {
        float r[4];
        upk2(r[0], r[1], acc2[i][0]);
        upk2(r[2], r[3], acc2[i][1]);
        *(float4*)&Sp[i * LL] = make_float4(r[0], r[1], r[2], r[3]);
    }
}

// ---------------------------------------------------------------------------
// Kernel 4: scatter (R3 coalesced form: consecutive float4 per lane).
// out[b, off(s)+j, :] = S[b,s,s+j] + A[b,s,:] + E[b,s+j,:]
// ---------------------------------------------------------------------------
__global__ __launch_bounds__(256) void scatter_kernel(float* __restrict__ out)
{
    const int s = blockIdx.x;
    const int b = blockIdx.y;

    __shared__ float  Ss[LL];
    __shared__ float4 As4[4];

    const int nE = LL - s;
    const float* Srow = g_S + (size_t)b * LL * LL + (size_t)s * LL + s;
    for (int i = threadIdx.x; i < nE; i += 256) Ss[i] = Srow[i];
    if (threadIdx.x < 4)
        As4[threadIdx.x] = ((const float4*)(g_A + (b * LL + s) * NOUT))[threadIdx.x];
    __syncthreads();

    const int base = b * NP + s * LL - (s * (s - 1)) / 2;
    const float4* E4   = (const float4*)(g_E + b * LL * NOUT) + (size_t)s * 4;
    float4*       out4 = (float4*)(out + (size_t)base * NOUT);

    const int total4 = nE * 4;
    for (int idx = threadIdx.x; idx < total4; idx += 256) {
        int j = idx >> 2, oq = idx & 3;
        float4 ev = E4[idx];
        float4 av = As4[oq];
        float  sv = Ss[j];
        out4[idx] = make_float4(sv + av.x + ev.x, sv + av.y + ev.y,
                                sv + av.z + ev.z, sv + av.w + ev.w);
    }
}

extern "C" void kernel_launch(void* const* d_in, const int* in_sizes, int n_in,
                              void* d_out, int out_size)
{
    const float* x  = (const float*)d_in[0];
    const float* Wq = (const float*)d_in[1];
    const float* bq = (const float*)d_in[2];
    const float* Wk = (const float*)d_in[3];
    const float* bk = (const float*)d_in[4];
    const float* Wb = (const float*)d_in[5];
    const float* bb = (const float*)d_in[6];
    float* out = (float*)d_out;

    proj_partial_kernel<<<256, 256>>>(x, Wq, Wk);
    reduce_ae_kernel<<<64, 256>>>(bq, bk, bb, Wb);
    dim3 g2(LL / 64, LL / 64, BN);
    score_kernel<<<g2, 256>>>();
    dim3 g3(LL, BN);
    scatter_kernel<<<g3, 256>>>(out);
}

// round 7
// speedup vs baseline: 1.5663x; 1.5663x over previous
#include <cuda_runtime.h>

#define BN   4
#define LL   512
#define HH   768
#define HSZ  64
#define NOUT 16
#define NTOK (BN*LL)      // 2048
#define NP   131328       // L*(L+1)/2
#define NKQ  16           // split-K factor
#define KQ   (HH/NKQ)     // 48

// scratch (allocation-free rule: __device__ globals)
__device__ float g_part[NKQ*NTOK*128]; // 16 MB split-K partials [kq][tok][n]
__device__ float g_q[NTOK*HSZ];        // 512 KB
__device__ float g_k[NTOK*HSZ];        // 512 KB
__device__ float g_A[NTOK*NOUT];       // 128 KB
__device__ float g_E[NTOK*NOUT];       // 128 KB
__device__ float g_S[BN*LL*LL];        // 4 MB

// ---------------------------------------------------------------------------
// Kernel 1: split-K partial GEMM, occupancy-first shape.
// 128-thread blocks; tile = 64 tokens x 64 cols; per-thread 8 tok x 4 col.
// Grid = 32 token-tiles x 2 col-halves (q|k) x 16 K-slices = 1024 blocks.
// ~55 regs, 8.6 KB smem -> ~10 blocks/SM -> ~7 warps/SMSP for latency hiding.
// ---------------------------------------------------------------------------
__global__ __launch_bounds__(128) void proj_partial_kernel(
    const float* __restrict__ x,
    const float* __restrict__ Wq,
    const float* __restrict__ Wk)
{
    __shared__ float xs[16][68];     // [k][token]  (68: float4-aligned rows)
    __shared__ float ws[16][64];     // [k][col within half]

    const int tid = threadIdx.x;
    const int bi  = blockIdx.x;
    const int tt  = bi & 31;                   // token tile (64 tokens)
    const int cc  = (bi >> 5) & 1;             // 0 -> Wq half, 1 -> Wk half
    const int kq  = bi >> 6;                   // K slice
    const int t0  = tt * 64;
    const int k0  = kq * KQ;
    const float* __restrict__ W = cc ? Wk : Wq;

    const int n0 = (tid & 15) * 4;             // 4 cols
    const int m0 = (tid >> 4) * 8;             // 8 tokens

    float acc[8][4];
    #pragma unroll
    for (int i = 0; i < 8; i++)
        #pragma unroll
        for (int j = 0; j < 4; j++) acc[i][j] = 0.f;

    for (int kk = k0; kk < k0 + KQ; kk += 16) {
        #pragma unroll
        for (int p = 0; p < 8; p++) {
            int e = tid + p * 128;
            int tok = e >> 4, d = e & 15;
            xs[d][tok] = x[(t0 + tok) * HH + kk + d];
        }
        #pragma unroll
        for (int p = 0; p < 8; p++) {
            int e = tid + p * 128;
            int n = e & 63, d = e >> 6;
            ws[d][n] = W[(kk + d) * HSZ + n];
        }
        __syncthreads();
        #pragma unroll
        for (int kd = 0; kd < 16; kd++) {
            float4 a0 = *(const float4*)&xs[kd][m0];
            float4 a1 = *(const float4*)&xs[kd][m0 + 4];
            float4 w0 = *(const float4*)&ws[kd][n0];
            float am[8] = {a0.x, a0.y, a0.z, a0.w, a1.x, a1.y, a1.z, a1.w};
            float wn[4] = {w0.x, w0.y, w0.z, w0.w};
            #pragma unroll
            for (int i = 0; i < 8; i++)
                #pragma unroll
                for (int j = 0; j < 4; j++) acc[i][j] += am[i] * wn[j];
        }
        __syncthreads();
    }

    // write partials: cols cc*64 + n0 .. +3 for tokens t0+m0 .. +7
    #pragma unroll
    for (int i = 0; i < 8; i++) {
        float* gp = g_part + ((size_t)kq * NTOK + t0 + m0 + i) * 128 + cc * 64 + n0;
        *(float4*)gp = make_float4(acc[i][0], acc[i][1], acc[i][2], acc[i][3]);
    }
}

// ---------------------------------------------------------------------------
// Kernel 2: reduce split-K partials + bias -> g_q/g_k, then A/E tables with
// Wb staged in shared. 64 blocks x 32 tokens. A/E in warp-uniform loops.
// A[s,o] = q[s]@Wb[0:64] + bb
// E[e,o] = k[e]@(Wb[64:128]+Wb[192:256]) + q[e]@Wb[128:192]
// ---------------------------------------------------------------------------
__global__ __launch_bounds__(256) void reduce_ae_kernel(
    const float* __restrict__ bq, const float* __restrict__ bk,
    const float* __restrict__ bb, const float* __restrict__ Wb)
{
    __shared__ float Wbs[256 * NOUT];
    __shared__ float sQK[32][132];
    __shared__ float bbs[NOUT];
    __shared__ float bqs[HSZ], bks[HSZ];

    const int tid = threadIdx.x;
    const int t0  = blockIdx.x * 32;

    #pragma unroll
    for (int p = 0; p < 16; p++)
        Wbs[tid + p * 256] = Wb[tid + p * 256];
    if (tid < NOUT) bbs[tid] = bb[tid];
    if (tid < HSZ)  { bqs[tid] = bq[tid]; bks[tid] = bk[tid]; }
    __syncthreads();

    const float4* gp4 = (const float4*)g_part;
    #pragma unroll
    for (int p = 0; p < 4; p++) {
        int e  = tid + p * 256;
        int tok = e >> 5, n4 = e & 31;
        size_t gi = (size_t)(t0 + tok) * 32 + n4;
        float4 v = make_float4(0.f, 0.f, 0.f, 0.f);
        #pragma unroll
        for (int q = 0; q < NKQ; q++) {
            float4 pv = gp4[(size_t)q * NTOK * 32 + gi];
            v.x += pv.x; v.y += pv.y; v.z += pv.z; v.w += pv.w;
        }
        int n = n4 * 4;
        if (n < 64) { v.x += bqs[n]; v.y += bqs[n+1]; v.z += bqs[n+2]; v.w += bqs[n+3]; }
        else        { v.x += bks[n-64]; v.y += bks[n-63]; v.z += bks[n-62]; v.w += bks[n-61]; }
        *(float4*)&sQK[tok][n] = v;
        int tok_g = t0 + tok;
        if (n4 < 16) ((float4*)(g_q + tok_g * HSZ))[n4]      = v;
        else         ((float4*)(g_k + tok_g * HSZ))[n4 - 16] = v;
    }
    __syncthreads();

    // A table: 32 tok x 16 o = 512 items (warp-uniform)
    #pragma unroll
    for (int p = 0; p < 2; p++) {
        int e2   = tid + p * 256;
        int tokL = e2 >> 4;
        int o    = e2 & 15;
        float a = bbs[o];
        #pragma unroll 8
        for (int h = 0; h < 64; h++)
            a += sQK[tokL][h] * Wbs[h * NOUT + o];
        g_A[(t0 + tokL) * NOUT + o] = a;
    }
    // E table: 32 tok x 16 o
    #pragma unroll
    for (int p = 0; p < 2; p++) {
        int e2   = tid + p * 256;
        int tokL = e2 >> 4;
        int o    = e2 & 15;
        float a = 0.f;
        #pragma unroll 8
        for (int h = 0; h < 64; h++) {
            a += sQK[tokL][64 + h] * (Wbs[(64 + h) * NOUT + o] + Wbs[(192 + h) * NOUT + o]);
            a += sQK[tokL][h]      *  Wbs[(128 + h) * NOUT + o];
        }
        g_E[(t0 + tokL) * NOUT + o] = a;
    }
}

// ---------------------------------------------------------------------------
// Kernel 3: S[b] = Q[b] @ K[b]^T (scalar FFMA, R3 form). 64x64 tiles;
// below-diagonal tiles early-exit.
// ---------------------------------------------------------------------------
__global__ __launch_bounds__(256) void score_kernel()
{
    const int bx = blockIdx.x;   // e tile
    const int by = blockIdx.y;   // s tile
    if (by > bx) return;
    const int b  = blockIdx.z;

    __shared__ float qs[64][68];
    __shared__ float ks[64][68];

    const int tid = threadIdx.x;
    const float* qb = g_q + (b * LL + by * 64) * HSZ;
    const float* kb = g_k + (b * LL + bx * 64) * HSZ;

    #pragma unroll
    for (int p = 0; p < 16; p++) {
        int e = tid + p * 256;
        int r = e >> 6, h = e & 63;
        qs[h][r] = qb[r * HSZ + h];
        ks[h][r] = kb[r * HSZ + h];
    }
    __syncthreads();

    const int m0 = (tid >> 4) * 4;
    const int n0 = (tid & 15) * 4;
    float acc[4][4];
    #pragma unroll
    for (int i = 0; i < 4; i++)
        #pragma unroll
        for (int j = 0; j < 4; j++) acc[i][j] = 0.f;

    #pragma unroll
    for (int h = 0; h < 64; h++) {
        float4 a = *(const float4*)&qs[h][m0];
        float4 v = *(const float4*)&ks[h][n0];
        float am[4] = {a.x, a.y, a.z, a.w};
        float vn[4] = {v.x, v.y, v.z, v.w};
        #pragma unroll
        for (int i = 0; i < 4; i++)
            #pragma unroll
            for (int j = 0; j < 4; j++) acc[i][j] += am[i] * vn[j];
    }

    float* Sp = g_S + (size_t)b * LL * LL + (by * 64 + m0) * LL + bx * 64 + n0;
    #pragma unroll
    for (int i = 0; i < 4; i++)
        *(float4*)&Sp[i * LL] = make_float4(acc[i][0], acc[i][1], acc[i][2], acc[i][3]);
}

// ---------------------------------------------------------------------------
// Kernel 4: scatter (R3 coalesced form: consecutive float4 per lane).
// out[b, off(s)+j, :] = S[b,s,s+j] + A[b,s,:] + E[b,s+j,:]
// ---------------------------------------------------------------------------
__global__ __launch_bounds__(256) void scatter_kernel(float* __restrict__ out)
{
    const int s = blockIdx.x;
    const int b = blockIdx.y;

    __shared__ float  Ss[LL];
    __shared__ float4 As4[4];

    const int nE = LL - s;
    const float* Srow = g_S + (size_t)b * LL * LL + (size_t)s * LL + s;
    for (int i = threadIdx.x; i < nE; i += 256) Ss[i] = Srow[i];
    if (threadIdx.x < 4)
        As4[threadIdx.x] = ((const float4*)(g_A + (b * LL + s) * NOUT))[threadIdx.x];
    __syncthreads();

    const int base = b * NP + s * LL - (s * (s - 1)) / 2;
    const float4* E4   = (const float4*)(g_E + b * LL * NOUT) + (size_t)s * 4;
    float4*       out4 = (float4*)(out + (size_t)base * NOUT);

    const int total4 = nE * 4;
    for (int idx = threadIdx.x; idx < total4; idx += 256) {
        int j = idx >> 2, oq = idx & 3;
        float4 ev = E4[idx];
        float4 av = As4[oq];
        float  sv = Ss[j];
        out4[idx] = make_float4(sv + av.x + ev.x, sv + av.y + ev.y,
                                sv + av.z + ev.z, sv + av.w + ev.w);
    }
}

extern "C" void kernel_launch(void* const* d_in, const int* in_sizes, int n_in,
                              void* d_out, int out_size)
{
    const float* x  = (const float*)d_in[0];
    const float* Wq = (const float*)d_in[1];
    const float* bq = (const float*)d_in[2];
    const float* Wk = (const float*)d_in[3];
    const float* bk = (const float*)d_in[4];
    const float* Wb = (const float*)d_in[5];
    const float* bb = (const float*)d_in[6];
    float* out = (float*)d_out;

    proj_partial_kernel<<<1024, 128>>>(x, Wq, Wk);
    reduce_ae_kernel<<<64, 256>>>(bq, bk, bb, Wb);
    dim3 g2(LL / 64, LL / 64, BN);
    score_kernel<<<g2, 256>>>();
    dim3 g3(LL, BN);
    scatter_kernel<<<g3, 256>>>(out);
}